// round 7
// baseline (speedup 1.0000x reference)
#include <cuda_runtime.h>
#include <stdint.h>

#define B_ 4
#define N_ 1024
#define D_ 64
#define NN (B_ * N_ * N_)

typedef unsigned long long ull;

// Scratch (device globals — no allocation allowed)
__device__ float g_hs[B_ * N_ * D_];
__device__ float g_hd[B_ * N_ * D_];
__device__ float g_t [B_ * N_];        // 0.25 * sum_d w2[d]*(hs+hd)  per node

// ---------------------------------------------------------------------------
// f32x2 packed helpers (sm_103a)
// ---------------------------------------------------------------------------
__device__ __forceinline__ ull add2(ull a, ull b) {
    ull r; asm("add.rn.f32x2 %0, %1, %2;" : "=l"(r) : "l"(a), "l"(b)); return r;
}
__device__ __forceinline__ ull fma2(ull a, ull b, ull c) {
    ull r; asm("fma.rn.f32x2 %0, %1, %2, %3;" : "=l"(r) : "l"(a), "l"(b), "l"(c)); return r;
}
__device__ __forceinline__ ull pack2(float v) {
    ull r; unsigned u = __float_as_uint(v);
    asm("mov.b64 %0, {%1, %2};" : "=l"(r) : "r"(u), "r"(u)); return r;
}
__device__ __forceinline__ void unpack2(ull v, float& lo, float& hi) {
    unsigned a, b; asm("mov.b64 {%0, %1}, %2;" : "=r"(a), "=r"(b) : "l"(v));
    lo = __uint_as_float(a); hi = __uint_as_float(b);
}
__device__ __forceinline__ float lo32(ull v) {
    unsigned a, b; asm("mov.b64 {%0, %1}, %2;" : "=r"(a), "=r"(b) : "l"(v));
    return __uint_as_float(a);
}

// ---------------------------------------------------------------------------
// Kernel 1: h_src = f @ W1[:D]; h_dst = f @ W1[D:] + b1; t = 0.25*w2.(hs+hd)
// ---------------------------------------------------------------------------
__global__ void proj_kernel(const float* __restrict__ f,
                            const float* __restrict__ W1,
                            const float* __restrict__ b1,
                            const float* __restrict__ W2) {
    __shared__ __align__(16) float w1s[128][64];
    __shared__ __align__(16) float fs[16][64];
    int tid = threadIdx.x;
    for (int t = tid; t < 128 * 64 / 4; t += 256)
        ((float4*)w1s)[t] = ((const float4*)W1)[t];
    int rowbase = blockIdx.x * 16;
    for (int t = tid; t < 16 * 64 / 4; t += 256)
        ((float4*)fs)[t] = ((const float4*)(f + rowbase * 64))[t];
    __syncthreads();

    int r = tid >> 4;
    int d0 = (tid & 15) * 4;
    float4 hs = make_float4(0.f, 0.f, 0.f, 0.f);
    float4 hd = make_float4(0.f, 0.f, 0.f, 0.f);
#pragma unroll 8
    for (int k = 0; k < 64; ++k) {
        float fv = fs[r][k];
        float4 ws = *(const float4*)&w1s[k][d0];
        float4 wd = *(const float4*)&w1s[64 + k][d0];
        hs.x = fmaf(fv, ws.x, hs.x); hs.y = fmaf(fv, ws.y, hs.y);
        hs.z = fmaf(fv, ws.z, hs.z); hs.w = fmaf(fv, ws.w, hs.w);
        hd.x = fmaf(fv, wd.x, hd.x); hd.y = fmaf(fv, wd.y, hd.y);
        hd.z = fmaf(fv, wd.z, hd.z); hd.w = fmaf(fv, wd.w, hd.w);
    }
    float4 bb = *(const float4*)&b1[d0];
    hd.x += bb.x; hd.y += bb.y; hd.z += bb.z; hd.w += bb.w;
    int row = rowbase + r;
    *(float4*)&g_hs[row * 64 + d0] = hs;
    *(float4*)&g_hd[row * 64 + d0] = hd;

    float4 w2v = *(const float4*)&W2[d0];
    float pt = (hs.x + hd.x) * w2v.x + (hs.y + hd.y) * w2v.y +
               (hs.z + hd.z) * w2v.z + (hs.w + hd.w) * w2v.w;
#pragma unroll
    for (int m = 8; m >= 1; m >>= 1)
        pt += __shfl_xor_sync(0xffffffffu, pt, m);
    if ((tid & 15) == 0) g_t[row] = 0.25f * pt;
}

// ---------------------------------------------------------------------------
// Kernel A: symmetric logits, tile pair (ib<=jb), 32x32 each.
//   S = sum_d 0.25*w|hs_i + hd_j| ; sym = t_i + t_j + b2 + S1[i][j] + S2[j][i]
// Writes lg (= out + NN) only.
// ---------------------------------------------------------------------------
struct MainSmem {
    ull  sAi[32][34];   // (hs_i, hs_i) packed, [d][row]
    ull  sAj[32][34];
    float sCi[32][36];  // hd_i [d][col]
    float sCj[32][36];
};
struct EpiSmem {
    float S1[32][36];
    float S2[32][36];
};
union FusedSmem { MainSmem m; EpiSmem e; };

__global__ __launch_bounds__(128, 8)
void logits_kernel(const float* __restrict__ W2,
                   const float* __restrict__ b2,
                   float* __restrict__ out) {
    __shared__ __align__(16) FusedSmem sm;
    __shared__ __align__(16) ull sW[64];    // (0.25*w2, 0.25*w2)
    __shared__ float stI[32], stJ[32];

    int tid = threadIdx.x;
    int b = blockIdx.y;
    int p = blockIdx.x;
    // decode p -> (ib <= jb), p = jb*(jb+1)/2 + ib
    int jb = (int)((sqrtf(8.0f * (float)p + 1.0f) - 1.0f) * 0.5f);
    while (jb * (jb + 1) / 2 > p) --jb;
    while ((jb + 1) * (jb + 2) / 2 <= p) ++jb;
    int ib = p - jb * (jb + 1) / 2;

    if (tid < 64) sW[tid] = pack2(0.25f * W2[tid]);
    if (tid >= 64 && tid < 96)  stI[tid - 64] = g_t[b * N_ + ib * 32 + (tid - 64)];
    if (tid >= 96)              stJ[tid - 96] = g_t[b * N_ + jb * 32 + (tid - 96)];

    const float* hsI = g_hs + ((size_t)b * N_ + ib * 32) * 64;
    const float* hsJ = g_hs + ((size_t)b * N_ + jb * 32) * 64;
    const float* hdI = g_hd + ((size_t)b * N_ + ib * 32) * 64;
    const float* hdJ = g_hd + ((size_t)b * N_ + jb * 32) * 64;

    int grp = tid >> 6;           // 0: tile1 (i-rows x j-cols), 1: tile2
    int g = tid & 63;
    int r0 = (g >> 3) * 4, c0 = (g & 7) * 4;

    ull acc01[4]; ull accP = 0ull;
    float accS[6];
#pragma unroll
    for (int r = 0; r < 4; ++r) acc01[r] = 0ull;
#pragma unroll
    for (int q = 0; q < 6; ++q) accS[q] = 0.f;

    const ull ABSM = 0x7FFFFFFF7FFFFFFFull;

    for (int kc = 0; kc < 2; ++kc) {
        __syncthreads();
        for (int t = tid; t < 256; t += 128) {
            int rr = t >> 3, q = (t & 7) * 4;
            float4 a1 = *(const float4*)&hsI[rr * 64 + kc * 32 + q];
            float4 a2 = *(const float4*)&hsJ[rr * 64 + kc * 32 + q];
            float4 c1 = *(const float4*)&hdI[rr * 64 + kc * 32 + q];
            float4 c2 = *(const float4*)&hdJ[rr * 64 + kc * 32 + q];
            sm.m.sAi[q + 0][rr] = pack2(a1.x); sm.m.sAi[q + 1][rr] = pack2(a1.y);
            sm.m.sAi[q + 2][rr] = pack2(a1.z); sm.m.sAi[q + 3][rr] = pack2(a1.w);
            sm.m.sAj[q + 0][rr] = pack2(a2.x); sm.m.sAj[q + 1][rr] = pack2(a2.y);
            sm.m.sAj[q + 2][rr] = pack2(a2.z); sm.m.sAj[q + 3][rr] = pack2(a2.w);
            sm.m.sCi[q + 0][rr] = c1.x; sm.m.sCi[q + 1][rr] = c1.y;
            sm.m.sCi[q + 2][rr] = c1.z; sm.m.sCi[q + 3][rr] = c1.w;
            sm.m.sCj[q + 0][rr] = c2.x; sm.m.sCj[q + 1][rr] = c2.y;
            sm.m.sCj[q + 2][rr] = c2.z; sm.m.sCj[q + 3][rr] = c2.w;
        }
        __syncthreads();

        const ull*  aB = grp ? &sm.m.sAj[0][0] : &sm.m.sAi[0][0];
        const float* cB = grp ? &sm.m.sCi[0][0] : &sm.m.sCj[0][0];

#pragma unroll 8
        for (int dd = 0; dd < 32; ++dd) {
            ull w = sW[kc * 32 + dd];
            ulonglong2 aa01 = *(const ulonglong2*)(aB + dd * 34 + r0);
            ulonglong2 aa23 = *(const ulonglong2*)(aB + dd * 34 + r0 + 2);
            ulonglong2 cc   = *(const ulonglong2*)(cB + dd * 36 + c0);
            ull x;
            x = add2(aa01.x, cc.x); acc01[0] = fma2(x & ABSM, w, acc01[0]);
            x = add2(aa01.y, cc.x); acc01[1] = fma2(x & ABSM, w, acc01[1]);
            x = add2(aa23.x, cc.x); acc01[2] = fma2(x & ABSM, w, acc01[2]);
            x = add2(aa23.y, cc.x); acc01[3] = fma2(x & ABSM, w, acc01[3]);
            x = add2(aa01.x, cc.y); accP     = fma2(x & ABSM, w, accP);
            float ws = lo32(w);
            float a1 = lo32(aa01.y), a2 = lo32(aa23.x), a3 = lo32(aa23.y);
            float cv2, cv3; unpack2(cc.y, cv2, cv3);
            accS[0] = fmaf(fabsf(a1 + cv2), ws, accS[0]);
            accS[1] = fmaf(fabsf(a1 + cv3), ws, accS[1]);
            accS[2] = fmaf(fabsf(a2 + cv2), ws, accS[2]);
            accS[3] = fmaf(fabsf(a2 + cv3), ws, accS[3]);
            accS[4] = fmaf(fabsf(a3 + cv2), ws, accS[4]);
            accS[5] = fmaf(fabsf(a3 + cv3), ws, accS[5]);
        }
    }
    __syncthreads();

    float* Sd = grp ? &sm.e.S2[0][0] : &sm.e.S1[0][0];
    {
        float4 o;
        unpack2(acc01[0], o.x, o.y);
        unpack2(accP, o.z, o.w);
        *(float4*)(Sd + r0 * 36 + c0) = o;
#pragma unroll
        for (int r = 1; r < 4; ++r) {
            unpack2(acc01[r], o.x, o.y);
            o.z = accS[(r - 1) * 2]; o.w = accS[(r - 1) * 2 + 1];
            *(float4*)(Sd + (r0 + r) * 36 + c0) = o;
        }
    }
    __syncthreads();

    float b2v = b2[0];
    float* lg = out + (size_t)NN;

    int ti = tid >> 2;
    int tj0 = (tid & 3) * 8;

#pragma unroll
    for (int reg = 0; reg < 2; ++reg) {
        int rowblk = reg ? jb : ib;
        int colblk = reg ? ib : jb;
        const float* Sa = reg ? &sm.e.S2[0][0] : &sm.e.S1[0][0];
        const float* Sb = reg ? &sm.e.S1[0][0] : &sm.e.S2[0][0];
        const float* tR = reg ? stJ : stI;
        const float* tC = reg ? stI : stJ;
        int i = rowblk * 32 + ti;
        size_t rowidx = ((size_t)b * N_ + i) * N_ + colblk * 32;
        float tRv = tR[ti] + b2v;
        float4 lgv[2];
#pragma unroll
        for (int c = 0; c < 8; ++c) {
            int tj = tj0 + c;
            ((float*)lgv)[c] = tRv + tC[tj] + Sa[ti * 36 + tj] + Sb[tj * 36 + ti];
        }
        *(float4*)(lg + rowidx + tj0) = lgv[0];
        *(float4*)(lg + rowidx + tj0 + 4) = lgv[1];
    }
}

// ---------------------------------------------------------------------------
// Threefry2x32, key (0,42), 20 rounds; partitionable: bits = o0 ^ o1.
// ---------------------------------------------------------------------------
__device__ __forceinline__ uint32_t threefry_xor(uint32_t x0, uint32_t x1) {
    const uint32_t ks0 = 0u, ks1 = 42u, ks2 = 0x1BD11BDAu ^ 0u ^ 42u;
    x0 += ks0; x1 += ks1;
#define TF_RND(r) { x0 += x1; x1 = __funnelshift_l(x1, x1, (r)); x1 ^= x0; }
    TF_RND(13) TF_RND(15) TF_RND(26) TF_RND(6)   x0 += ks1; x1 += ks2 + 1u;
    TF_RND(17) TF_RND(29) TF_RND(16) TF_RND(24)  x0 += ks2; x1 += ks0 + 2u;
    TF_RND(13) TF_RND(15) TF_RND(26) TF_RND(6)   x0 += ks0; x1 += ks1 + 3u;
    TF_RND(17) TF_RND(29) TF_RND(16) TF_RND(24)  x0 += ks1; x1 += ks2 + 4u;
    TF_RND(13) TF_RND(15) TF_RND(26) TF_RND(6)   x0 += ks2; x1 += ks0 + 5u;
#undef TF_RND
    return x0 ^ x1;
}

__device__ __forceinline__ float u_from_bits(uint32_t bits) {
    float f = __uint_as_float((bits >> 9) | 0x3f800000u) - 1.0f;
    return fmaxf(f, 1.17549435e-38f);
}

// ---------------------------------------------------------------------------
// Kernel B: gumbel hard-sample, pure streaming at full occupancy.
//   adj[idx] = (exp(s)*E1 >= E0) * (i != j), E = -log(u)
// Fast path via MUFU (__logf/__expf); precise recompute when margin < 1e-4.
// ---------------------------------------------------------------------------
__global__ __launch_bounds__(256)
void gumbel_kernel(float* __restrict__ out) {
    const float* lg = out + (size_t)NN;
    float* adj = out;
    int base = (blockIdx.x * 256 + threadIdx.x) * 8;

    float4 s0 = *(const float4*)(lg + base);
    float4 s1 = *(const float4*)(lg + base + 4);
    float4 a0, a1;

#pragma unroll
    for (int c = 0; c < 8; ++c) {
        int idx = base + c;
        float sv = (c < 4) ? ((const float*)&s0)[c] : ((const float*)&s1)[c - 4];
        uint32_t L0 = ((uint32_t)idx) << 1;
        float u0 = u_from_bits(threefry_xor(0u, L0));
        float u1 = u_from_bits(threefry_xor(0u, L0 + 1u));
        // fast path (MUFU)
        float E0 = -__logf(u0);
        float E1 = -__logf(u1);
        float lhs = __expf(sv) * E1;
        bool take;
        float margin = fabsf(lhs - E0);
        if (margin >= 1e-4f * (lhs + E0)) {
            take = lhs >= E0;
        } else {
            // precise recompute (matches R6-verified path)
            float E0p = -logf(u0);
            float E1p = -logf(u1);
            take = expf(sv) * E1p >= E0p;
        }
        int r = idx & (N_ * N_ - 1);
        int i = r >> 10, j = r & (N_ - 1);
        float v = (take && (i != j)) ? 1.f : 0.f;
        if (c < 4) ((float*)&a0)[c] = v; else ((float*)&a1)[c - 4] = v;
    }
    *(float4*)(adj + base) = a0;
    *(float4*)(adj + base + 4) = a1;
}

// ---------------------------------------------------------------------------
extern "C" void kernel_launch(void* const* d_in, const int* in_sizes, int n_in,
                              void* d_out, int out_size) {
    const float* f  = (const float*)d_in[0];
    const float* W1 = (const float*)d_in[1];
    const float* b1 = (const float*)d_in[2];
    const float* W2 = (const float*)d_in[3];
    const float* b2 = (const float*)d_in[4];

    proj_kernel<<<(B_ * N_) / 16, 256>>>(f, W1, b1, W2);
    int npairs = (N_ / 32) * (N_ / 32 + 1) / 2;  // 528
    logits_kernel<<<dim3(npairs, B_), 128>>>(W2, b2, (float*)d_out);
    gumbel_kernel<<<NN / (256 * 8), 256>>>((float*)d_out);
}

// round 8
// speedup vs baseline: 1.0763x; 1.0763x over previous
#include <cuda_runtime.h>
#include <stdint.h>

#define B_ 4
#define N_ 1024
#define D_ 64
#define NN (B_ * N_ * N_)

typedef unsigned long long ull;

// Scratch (device globals — no allocation allowed)
__device__ float g_hs[B_ * N_ * D_];
__device__ float g_hd[B_ * N_ * D_];
__device__ float g_ths[B_ * N_];   // 0.25 * w2.hs per node
__device__ float g_thd[B_ * N_];   // 0.25 * w2.hd per node (incl b1)

// ---------------------------------------------------------------------------
// f32x2 packed helpers (sm_103a)
// ---------------------------------------------------------------------------
__device__ __forceinline__ ull add2(ull a, ull b) {
    ull r; asm("add.rn.f32x2 %0, %1, %2;" : "=l"(r) : "l"(a), "l"(b)); return r;
}
__device__ __forceinline__ ull fma2(ull a, ull b, ull c) {
    ull r; asm("fma.rn.f32x2 %0, %1, %2, %3;" : "=l"(r) : "l"(a), "l"(b), "l"(c)); return r;
}
__device__ __forceinline__ ull pack2(float v) {
    ull r; unsigned u = __float_as_uint(v);
    asm("mov.b64 %0, {%1, %2};" : "=l"(r) : "r"(u), "r"(u)); return r;
}
__device__ __forceinline__ void unpack2(ull v, float& lo, float& hi) {
    unsigned a, b; asm("mov.b64 {%0, %1}, %2;" : "=r"(a), "=r"(b) : "l"(v));
    lo = __uint_as_float(a); hi = __uint_as_float(b);
}
__device__ __forceinline__ float lo32(ull v) {
    unsigned a, b; asm("mov.b64 {%0, %1}, %2;" : "=r"(a), "=r"(b) : "l"(v));
    return __uint_as_float(a);
}

// ---------------------------------------------------------------------------
// Kernel 1: split-half projection.
// blockIdx.y = 0: hs = f @ W1[:64]          (+ t-partial)
// blockIdx.y = 1: hd = f @ W1[64:] + b1     (+ t-partial)
// 256 threads = 16 rows x 16 d-quads; stages 16KB of W1 half + f tile.
// ---------------------------------------------------------------------------
__global__ void proj_kernel(const float* __restrict__ f,
                            const float* __restrict__ W1,
                            const float* __restrict__ b1,
                            const float* __restrict__ W2) {
    __shared__ __align__(16) float w1s[64][64];
    __shared__ __align__(16) float fs[16][64];
    int tid = threadIdx.x;
    int half = blockIdx.y;
    const float* w1base = W1 + half * 64 * 64;
    for (int t = tid; t < 64 * 64 / 4; t += 256)
        ((float4*)w1s)[t] = ((const float4*)w1base)[t];
    int rowbase = blockIdx.x * 16;
    for (int t = tid; t < 16 * 64 / 4; t += 256)
        ((float4*)fs)[t] = ((const float4*)(f + rowbase * 64))[t];
    __syncthreads();

    int r = tid >> 4;
    int d0 = (tid & 15) * 4;
    float4 h = make_float4(0.f, 0.f, 0.f, 0.f);
#pragma unroll 8
    for (int k = 0; k < 64; ++k) {
        float fv = fs[r][k];
        float4 w = *(const float4*)&w1s[k][d0];
        h.x = fmaf(fv, w.x, h.x); h.y = fmaf(fv, w.y, h.y);
        h.z = fmaf(fv, w.z, h.z); h.w = fmaf(fv, w.w, h.w);
    }
    int row = rowbase + r;
    if (half) {
        float4 bb = *(const float4*)&b1[d0];
        h.x += bb.x; h.y += bb.y; h.z += bb.z; h.w += bb.w;
        *(float4*)&g_hd[row * 64 + d0] = h;
    } else {
        *(float4*)&g_hs[row * 64 + d0] = h;
    }

    float4 w2v = *(const float4*)&W2[d0];
    float pt = h.x * w2v.x + h.y * w2v.y + h.z * w2v.z + h.w * w2v.w;
#pragma unroll
    for (int m = 8; m >= 1; m >>= 1)
        pt += __shfl_xor_sync(0xffffffffu, pt, m);
    if ((tid & 15) == 0) {
        if (half) g_thd[row] = 0.25f * pt;
        else      g_ths[row] = 0.25f * pt;
    }
}

// ---------------------------------------------------------------------------
// Threefry2x32, key (0,42), 20 rounds; partitionable: bits = o0 ^ o1.
// ---------------------------------------------------------------------------
__device__ __forceinline__ uint32_t threefry_xor(uint32_t x0, uint32_t x1) {
    const uint32_t ks0 = 0u, ks1 = 42u, ks2 = 0x1BD11BDAu ^ 0u ^ 42u;
    x0 += ks0; x1 += ks1;
#define TF_RND(r) { x0 += x1; x1 = __funnelshift_l(x1, x1, (r)); x1 ^= x0; }
    TF_RND(13) TF_RND(15) TF_RND(26) TF_RND(6)   x0 += ks1; x1 += ks2 + 1u;
    TF_RND(17) TF_RND(29) TF_RND(16) TF_RND(24)  x0 += ks2; x1 += ks0 + 2u;
    TF_RND(13) TF_RND(15) TF_RND(26) TF_RND(6)   x0 += ks0; x1 += ks1 + 3u;
    TF_RND(17) TF_RND(29) TF_RND(16) TF_RND(24)  x0 += ks1; x1 += ks2 + 4u;
    TF_RND(13) TF_RND(15) TF_RND(26) TF_RND(6)   x0 += ks2; x1 += ks0 + 5u;
#undef TF_RND
    return x0 ^ x1;
}

__device__ __forceinline__ float u_from_bits(uint32_t bits) {
    float f = __uint_as_float((bits >> 9) | 0x3f800000u) - 1.0f;
    return fmaxf(f, 1.17549435e-38f);
}

// ---------------------------------------------------------------------------
// Fused kernel: tile pair (ib<=jb), 32x32 each.
//   S = sum_d 0.25*w|hs_i + hd_j| ; sym = t_i + t_j + b2 + S1[i][j] + S2[j][i]
// Epilogue: gumbel hard-sample with MUFU fast path + precise fallback.
// ---------------------------------------------------------------------------
struct MainSmem {
    ull  sAi[32][34];   // (hs_i, hs_i) packed, [d][row]
    ull  sAj[32][34];
    float sCi[32][36];  // hd_i [d][col]
    float sCj[32][36];
};
struct EpiSmem {
    float S1[32][36];
    float S2[32][36];
};
union FusedSmem { MainSmem m; EpiSmem e; };

__global__ __launch_bounds__(128, 8)
void fused_kernel(const float* __restrict__ W2,
                  const float* __restrict__ b2,
                  float* __restrict__ out) {
    __shared__ __align__(16) FusedSmem sm;
    __shared__ __align__(16) ull sW[64];    // (0.25*w2, 0.25*w2)
    __shared__ float stI[32], stJ[32];

    int tid = threadIdx.x;
    int b = blockIdx.y;
    int p = blockIdx.x;
    // decode p -> (ib <= jb), p = jb*(jb+1)/2 + ib
    int jb = (int)((sqrtf(8.0f * (float)p + 1.0f) - 1.0f) * 0.5f);
    while (jb * (jb + 1) / 2 > p) --jb;
    while ((jb + 1) * (jb + 2) / 2 <= p) ++jb;
    int ib = p - jb * (jb + 1) / 2;

    if (tid < 64) sW[tid] = pack2(0.25f * W2[tid]);
    if (tid >= 64 && tid < 96) {
        int q = tid - 64;
        stI[q] = g_ths[b * N_ + ib * 32 + q] + g_thd[b * N_ + ib * 32 + q];
    }
    if (tid >= 96) {
        int q = tid - 96;
        stJ[q] = g_ths[b * N_ + jb * 32 + q] + g_thd[b * N_ + jb * 32 + q];
    }

    const float* hsI = g_hs + ((size_t)b * N_ + ib * 32) * 64;
    const float* hsJ = g_hs + ((size_t)b * N_ + jb * 32) * 64;
    const float* hdI = g_hd + ((size_t)b * N_ + ib * 32) * 64;
    const float* hdJ = g_hd + ((size_t)b * N_ + jb * 32) * 64;

    int grp = tid >> 6;
    int g = tid & 63;
    int r0 = (g >> 3) * 4, c0 = (g & 7) * 4;

    ull acc01[4]; ull accP = 0ull;
    float accS[6];
#pragma unroll
    for (int r = 0; r < 4; ++r) acc01[r] = 0ull;
#pragma unroll
    for (int q = 0; q < 6; ++q) accS[q] = 0.f;

    const ull ABSM = 0x7FFFFFFF7FFFFFFFull;

    for (int kc = 0; kc < 2; ++kc) {
        __syncthreads();
        for (int t = tid; t < 256; t += 128) {
            int rr = t >> 3, q = (t & 7) * 4;
            float4 a1 = *(const float4*)&hsI[rr * 64 + kc * 32 + q];
            float4 a2 = *(const float4*)&hsJ[rr * 64 + kc * 32 + q];
            float4 c1 = *(const float4*)&hdI[rr * 64 + kc * 32 + q];
            float4 c2 = *(const float4*)&hdJ[rr * 64 + kc * 32 + q];
            sm.m.sAi[q + 0][rr] = pack2(a1.x); sm.m.sAi[q + 1][rr] = pack2(a1.y);
            sm.m.sAi[q + 2][rr] = pack2(a1.z); sm.m.sAi[q + 3][rr] = pack2(a1.w);
            sm.m.sAj[q + 0][rr] = pack2(a2.x); sm.m.sAj[q + 1][rr] = pack2(a2.y);
            sm.m.sAj[q + 2][rr] = pack2(a2.z); sm.m.sAj[q + 3][rr] = pack2(a2.w);
            sm.m.sCi[q + 0][rr] = c1.x; sm.m.sCi[q + 1][rr] = c1.y;
            sm.m.sCi[q + 2][rr] = c1.z; sm.m.sCi[q + 3][rr] = c1.w;
            sm.m.sCj[q + 0][rr] = c2.x; sm.m.sCj[q + 1][rr] = c2.y;
            sm.m.sCj[q + 2][rr] = c2.z; sm.m.sCj[q + 3][rr] = c2.w;
        }
        __syncthreads();

        const ull*  aB = grp ? &sm.m.sAj[0][0] : &sm.m.sAi[0][0];
        const float* cB = grp ? &sm.m.sCi[0][0] : &sm.m.sCj[0][0];

#pragma unroll 8
        for (int dd = 0; dd < 32; ++dd) {
            ull w = sW[kc * 32 + dd];
            ulonglong2 aa01 = *(const ulonglong2*)(aB + dd * 34 + r0);
            ulonglong2 aa23 = *(const ulonglong2*)(aB + dd * 34 + r0 + 2);
            ulonglong2 cc   = *(const ulonglong2*)(cB + dd * 36 + c0);
            ull x;
            x = add2(aa01.x, cc.x); acc01[0] = fma2(x & ABSM, w, acc01[0]);
            x = add2(aa01.y, cc.x); acc01[1] = fma2(x & ABSM, w, acc01[1]);
            x = add2(aa23.x, cc.x); acc01[2] = fma2(x & ABSM, w, acc01[2]);
            x = add2(aa23.y, cc.x); acc01[3] = fma2(x & ABSM, w, acc01[3]);
            x = add2(aa01.x, cc.y); accP     = fma2(x & ABSM, w, accP);
            float ws = lo32(w);
            float a1 = lo32(aa01.y), a2 = lo32(aa23.x), a3 = lo32(aa23.y);
            float cv2, cv3; unpack2(cc.y, cv2, cv3);
            accS[0] = fmaf(fabsf(a1 + cv2), ws, accS[0]);
            accS[1] = fmaf(fabsf(a1 + cv3), ws, accS[1]);
            accS[2] = fmaf(fabsf(a2 + cv2), ws, accS[2]);
            accS[3] = fmaf(fabsf(a2 + cv3), ws, accS[3]);
            accS[4] = fmaf(fabsf(a3 + cv2), ws, accS[4]);
            accS[5] = fmaf(fabsf(a3 + cv3), ws, accS[5]);
        }
    }
    __syncthreads();

    float* Sd = grp ? &sm.e.S2[0][0] : &sm.e.S1[0][0];
    {
        float4 o;
        unpack2(acc01[0], o.x, o.y);
        unpack2(accP, o.z, o.w);
        *(float4*)(Sd + r0 * 36 + c0) = o;
#pragma unroll
        for (int r = 1; r < 4; ++r) {
            unpack2(acc01[r], o.x, o.y);
            o.z = accS[(r - 1) * 2]; o.w = accS[(r - 1) * 2 + 1];
            *(float4*)(Sd + (r0 + r) * 36 + c0) = o;
        }
    }
    __syncthreads();

    float b2v = b2[0];
    float* adj = out;
    float* lg  = out + (size_t)NN;

    int ti = tid >> 2;
    int tj0 = (tid & 3) * 8;

#pragma unroll 1
    for (int reg = 0; reg < 2; ++reg) {
        int rowblk = reg ? jb : ib;
        int colblk = reg ? ib : jb;
        const float* Sa = reg ? &sm.e.S2[0][0] : &sm.e.S1[0][0];
        const float* Sb = reg ? &sm.e.S1[0][0] : &sm.e.S2[0][0];
        const float* tR = reg ? stJ : stI;
        const float* tC = reg ? stI : stJ;
        int i = rowblk * 32 + ti;
        size_t rowidx = ((size_t)b * N_ + i) * N_ + colblk * 32;
        float tRv = tR[ti] + b2v;
        float4 lgv[2], adv[2];
#pragma unroll 4
        for (int c = 0; c < 8; ++c) {
            int tj = tj0 + c;
            float sv = tRv + tC[tj] + Sa[ti * 36 + tj] + Sb[tj * 36 + ti];
            uint32_t idx32 = (uint32_t)(rowidx + tj);
            uint32_t L0 = idx32 << 1;
            float u0 = u_from_bits(threefry_xor(0u, L0));
            float u1 = u_from_bits(threefry_xor(0u, L0 + 1u));
            // fast path (MUFU)
            float E0 = -__logf(u0);
            float E1 = -__logf(u1);
            float lhs = __expf(sv) * E1;
            bool take;
            float margin = fabsf(lhs - E0);
            if (margin >= 1e-4f * (lhs + E0)) {
                take = lhs >= E0;
            } else {
                float E0p = -logf(u0);
                float E1p = -logf(u1);
                take = expf(sv) * E1p >= E0p;
            }
            int j = colblk * 32 + tj;
            float mask = (i == j) ? 0.f : 1.f;
            ((float*)lgv)[c] = sv;
            ((float*)adv)[c] = take ? mask : 0.f;
        }
        *(float4*)(lg + rowidx + tj0) = lgv[0];
        *(float4*)(lg + rowidx + tj0 + 4) = lgv[1];
        *(float4*)(adj + rowidx + tj0) = adv[0];
        *(float4*)(adj + rowidx + tj0 + 4) = adv[1];
    }
}

// ---------------------------------------------------------------------------
extern "C" void kernel_launch(void* const* d_in, const int* in_sizes, int n_in,
                              void* d_out, int out_size) {
    const float* f  = (const float*)d_in[0];
    const float* W1 = (const float*)d_in[1];
    const float* b1 = (const float*)d_in[2];
    const float* W2 = (const float*)d_in[3];
    const float* b2 = (const float*)d_in[4];

    proj_kernel<<<dim3((B_ * N_) / 16, 2), 256>>>(f, W1, b1, W2);
    int npairs = (N_ / 32) * (N_ / 32 + 1) / 2;  // 528
    fused_kernel<<<dim3(npairs, B_), 128>>>(W2, b2, (float*)d_out);
}